// round 1
// baseline (speedup 1.0000x reference)
#include <cuda_runtime.h>
#include <math.h>

#define T_LEN 1024
#define BATCH 32
#define DIN   256
#define HID   512
#define G4    2048
#define NB    128

__device__ float g_gx[(long)T_LEN * BATCH * G4];
__device__ float g_hs[(long)T_LEN * BATCH * HID];
__device__ float g_h[2][BATCH * HID];
__device__ unsigned g_arrive[NB];

__global__ __launch_bounds__(256) void gemm_input(
    const float* __restrict__ x, const float* __restrict__ Wih,
    const float* __restrict__ bih, const float* __restrict__ bhh) {
  __shared__ float xs[32][68];
  __shared__ float wsT[32][68];
  const int t0 = blockIdx.x * 64, n0 = blockIdx.y * 64, b = blockIdx.z;
  const int tid = threadIdx.x;
  const int tt4 = tid & 15, nn4 = tid >> 4;

  float acc[4][4];
#pragma unroll
  for (int i = 0; i < 4; i++)
#pragma unroll
    for (int j = 0; j < 4; j++) acc[i][j] = 0.f;

  for (int d0 = 0; d0 < DIN; d0 += 32) {
#pragma unroll
    for (int r = 0; r < 32; r += 4) {
      int dd = r + (tid >> 6);
      int tt = tid & 63;
      xs[dd][tt] = x[((long)b * DIN + d0 + dd) * T_LEN + t0 + tt];
    }
#pragma unroll
    for (int r = 0; r < 64; r += 8) {
      int nn = r + (tid >> 5);
      int dd = tid & 31;
      wsT[dd][nn] = Wih[(long)(n0 + nn) * DIN + d0 + dd];
    }
    __syncthreads();
#pragma unroll
    for (int dd = 0; dd < 32; dd++) {
      float4 a = *(const float4*)&xs[dd][tt4 * 4];
      float4 w = *(const float4*)&wsT[dd][nn4 * 4];
      acc[0][0] += a.x * w.x; acc[0][1] += a.x * w.y; acc[0][2] += a.x * w.z; acc[0][3] += a.x * w.w;
      acc[1][0] += a.y * w.x; acc[1][1] += a.y * w.y; acc[1][2] += a.y * w.z; acc[1][3] += a.y * w.w;
      acc[2][0] += a.z * w.x; acc[2][1] += a.z * w.y; acc[2][2] += a.z * w.z; acc[2][3] += a.z * w.w;
      acc[3][0] += a.w * w.x; acc[3][1] += a.w * w.y; acc[3][2] += a.w * w.z; acc[3][3] += a.w * w.w;
    }
    __syncthreads();
  }
  const int n = n0 + nn4 * 4;
  float4 b1 = *(const float4*)&bih[n];
  float4 b2 = *(const float4*)&bhh[n];
  float4 bv = make_float4(b1.x + b2.x, b1.y + b2.y, b1.z + b2.z, b1.w + b2.w);
#pragma unroll
  for (int i = 0; i < 4; i++) {
    int t = t0 + tt4 * 4 + i;
    float4 o = make_float4(acc[i][0] + bv.x, acc[i][1] + bv.y,
                           acc[i][2] + bv.z, acc[i][3] + bv.w);
    *(float4*)&g_gx[(long)t * (BATCH * G4) + (long)b * G4 + n] = o;
  }
}

__global__ void init_bar() {
  ((volatile unsigned*)g_arrive)[threadIdx.x] = 0u;
}

#define WPAD 516
#define SMEM_SCAN_FLOATS (16 * WPAD + 32 * WPAD + 8 * 32 * 16)
#define SMEM_SCAN_BYTES (SMEM_SCAN_FLOATS * 4)

__global__ __launch_bounds__(256, 1) void lstm_scan(const float* __restrict__ Whh) {
  extern __shared__ float sm[];
  float* Wsm = sm;
  float* hsm = sm + 16 * WPAD;
  float* red = hsm + 32 * WPAD;

  const int tid = threadIdx.x, blk = blockIdx.x;
  const int jj = tid & 3, bg = (tid >> 2) & 7, ks = tid >> 5;

  for (int r = 0; r < 16; r++) {
    int g = r >> 2, j4 = r & 3;
    long row = (long)(g * HID + blk * 4 + j4) * HID;
    for (int k = tid; k < HID; k += 256) Wsm[r * WPAD + k] = Whh[row + k];
  }
  __syncthreads();

  const float* w0 = Wsm + (0  + jj) * WPAD + ks * 64;
  const float* w1 = Wsm + (4  + jj) * WPAD + ks * 64;
  const float* w2 = Wsm + (8  + jj) * WPAD + ks * 64;
  const float* w3 = Wsm + (12 + jj) * WPAD + ks * 64;

  const int rb_b = tid >> 2, rb_j = tid & 3;
  float c_reg = 0.f;

  for (int t = 0; t < T_LEN; t++) {
    float gxv0 = 0.f, gxv1 = 0.f, gxv2 = 0.f, gxv3 = 0.f;
    if (tid < 128) {
      long base = (long)t * (BATCH * G4) + (long)rb_b * G4 + blk * 4 + rb_j;
      gxv0 = g_gx[base];
      gxv1 = g_gx[base + HID];
      gxv2 = g_gx[base + 2 * HID];
      gxv3 = g_gx[base + 3 * HID];
    }
    if (t == 0) {
      for (int i = tid; i < 32 * WPAD; i += 256) hsm[i] = 0.f;
    } else {
      const float4* hcur = (const float4*)g_h[t & 1];
      for (int i = tid * 4; i < BATCH * HID; i += 1024) {
        float4 v = __ldcg(hcur + (i >> 2));
        int b = i >> 9, k = i & 511;
        *(float4*)(hsm + b * WPAD + k) = v;
      }
    }
    __syncthreads();

    float acc[16];
#pragma unroll
    for (int q = 0; q < 16; q++) acc[q] = 0.f;
    {
      const float* hb = hsm + ks * 64;
#pragma unroll 4
      for (int kk = 0; kk < 64; kk += 4) {
        float4 wi = *(const float4*)(w0 + kk);
        float4 wf = *(const float4*)(w1 + kk);
        float4 wg = *(const float4*)(w2 + kk);
        float4 wo = *(const float4*)(w3 + kk);
#pragma unroll
        for (int b4 = 0; b4 < 4; b4++) {
          float4 hv = *(const float4*)(hb + (bg * 4 + b4) * WPAD + kk);
          acc[b4]      += wi.x * hv.x + wi.y * hv.y + wi.z * hv.z + wi.w * hv.w;
          acc[4 + b4]  += wf.x * hv.x + wf.y * hv.y + wf.z * hv.z + wf.w * hv.w;
          acc[8 + b4]  += wg.x * hv.x + wg.y * hv.y + wg.z * hv.z + wg.w * hv.w;
          acc[12 + b4] += wo.x * hv.x + wo.y * hv.y + wo.z * hv.z + wo.w * hv.w;
        }
      }
    }
    {
      float* rp = red + (ks * 32 + (tid & 31)) * 16;
#pragma unroll
      for (int q = 0; q < 16; q++) rp[q] = acc[q];
    }
    __syncthreads();

    if (tid < 128) {
      int cell = rb_j + 4 * (rb_b >> 2);
      int b4 = rb_b & 3;
      float s0 = gxv0, s1 = gxv1, s2 = gxv2, s3 = gxv3;
#pragma unroll
      for (int p = 0; p < 8; p++) {
        const float* q = red + (p * 32 + cell) * 16 + b4;
        s0 += q[0]; s1 += q[4]; s2 += q[8]; s3 += q[12];
      }
      float ig = 1.f / (1.f + __expf(-s0));
      float fg = 1.f / (1.f + __expf(-s1));
      float gg = tanhf(s2);
      float og = 1.f / (1.f + __expf(-s3));
      c_reg = fg * c_reg + ig * gg;
      float h = og * tanhf(c_reg);
      int j = blk * 4 + rb_j;
      __stcg(&g_h[(t + 1) & 1][rb_b * HID + j], h);
      g_hs[(long)t * (BATCH * HID) + rb_b * HID + j] = h;
    }

    __syncthreads();
    if (tid == 0) {
      __threadfence();
      ((volatile unsigned*)g_arrive)[blk] = (unsigned)(t + 1);
    }
    if (tid < 32) {
      const unsigned target = (unsigned)(t + 1);
      const volatile unsigned* fl = (const volatile unsigned*)g_arrive;
      bool ok;
      do {
        unsigned a = fl[tid], b = fl[tid + 32], c = fl[tid + 64], d = fl[tid + 96];
        bool mine = (a >= target) && (b >= target) && (c >= target) && (d >= target);
        ok = __all_sync(0xffffffffu, mine);
      } while (!ok);
    }
    __syncthreads();
  }
}

__global__ __launch_bounds__(256) void transpose_hs(float* __restrict__ out) {
  __shared__ float tile[32][33];
  const int t0 = blockIdx.x * 32, j0 = blockIdx.y * 32, b = blockIdx.z;
  const int tx = threadIdx.x, ty = threadIdx.y;
  for (int i = ty; i < 32; i += 8)
    tile[i][tx] = g_hs[(long)(t0 + i) * (BATCH * HID) + (long)b * HID + j0 + tx];
  __syncthreads();
  for (int i = ty; i < 32; i += 8)
    out[((long)b * HID + j0 + i) * T_LEN + t0 + tx] = tile[tx][i];
}

extern "C" void kernel_launch(void* const* d_in, const int* in_sizes, int n_in,
                              void* d_out, int out_size) {
  (void)in_sizes; (void)n_in; (void)out_size;
  const float* x   = (const float*)d_in[0];
  const float* Wih = (const float*)d_in[1];
  const float* Whh = (const float*)d_in[2];
  const float* bih = (const float*)d_in[3];
  const float* bhh = (const float*)d_in[4];
  float* out = (float*)d_out;

  cudaFuncSetAttribute(lstm_scan, cudaFuncAttributeMaxDynamicSharedMemorySize,
                       SMEM_SCAN_BYTES);

  dim3 g1(T_LEN / 64, G4 / 64, BATCH);
  gemm_input<<<g1, 256>>>(x, Wih, bih, bhh);

  init_bar<<<1, NB>>>();
  lstm_scan<<<NB, 256, SMEM_SCAN_BYTES>>>(Whh);

  dim3 g3(T_LEN / 32, HID / 32, BATCH);
  transpose_hs<<<g3, dim3(32, 8)>>>(out);
}

// round 2
// speedup vs baseline: 1.1029x; 1.1029x over previous
#include <cuda_runtime.h>
#include <math.h>
#include <stdint.h>

#define T_LEN 1024
#define BATCH 32
#define DIN   256
#define HID   512
#define G4    2048
#define NB    128
#define NT    512          // threads in scan
#define BH    (BATCH*HID)  // 16384

__device__ float g_gx[(long)T_LEN * BATCH * G4];   // [T][B][4H]
__device__ float g_hs[(long)T_LEN * BATCH * HID];  // [T][B][H]
__device__ unsigned g_arrive[NB];

// ---------------------------------------------------------------- helpers
__device__ __forceinline__ float fast_tanh(float x) {
  float y; asm("tanh.approx.f32 %0, %1;" : "=f"(y) : "f"(x)); return y;
}
__device__ __forceinline__ float fast_sig(float x) {
  return 0.5f * fast_tanh(0.5f * x) + 0.5f;
}
__device__ __forceinline__ void cp_async16(void* smem_dst, const void* gsrc) {
  uint32_t s = (uint32_t)__cvta_generic_to_shared(smem_dst);
  asm volatile("cp.async.cg.shared.global [%0], [%1], 16;\n" :: "r"(s), "l"(gsrc));
}

// ---------------- phase 1: gx = x^T @ W_ih^T + (b_ih + b_hh) ----------------
__global__ __launch_bounds__(256) void gemm_input(
    const float* __restrict__ x, const float* __restrict__ Wih,
    const float* __restrict__ bih, const float* __restrict__ bhh) {
  __shared__ float xs[32][68];
  __shared__ float wsT[32][68];
  const int t0 = blockIdx.x * 64, n0 = blockIdx.y * 64, b = blockIdx.z;
  const int tid = threadIdx.x;
  const int tt4 = tid & 15, nn4 = tid >> 4;

  float acc[4][4];
#pragma unroll
  for (int i = 0; i < 4; i++)
#pragma unroll
    for (int j = 0; j < 4; j++) acc[i][j] = 0.f;

  for (int d0 = 0; d0 < DIN; d0 += 32) {
#pragma unroll
    for (int r = 0; r < 32; r += 4) {
      int dd = r + (tid >> 6);
      int tt = tid & 63;
      xs[dd][tt] = x[((long)b * DIN + d0 + dd) * T_LEN + t0 + tt];
    }
#pragma unroll
    for (int r = 0; r < 64; r += 8) {
      int nn = r + (tid >> 5);
      int dd = tid & 31;
      wsT[dd][nn] = Wih[(long)(n0 + nn) * DIN + d0 + dd];
    }
    __syncthreads();
#pragma unroll
    for (int dd = 0; dd < 32; dd++) {
      float4 a = *(const float4*)&xs[dd][tt4 * 4];
      float4 w = *(const float4*)&wsT[dd][nn4 * 4];
      acc[0][0] += a.x * w.x; acc[0][1] += a.x * w.y; acc[0][2] += a.x * w.z; acc[0][3] += a.x * w.w;
      acc[1][0] += a.y * w.x; acc[1][1] += a.y * w.y; acc[1][2] += a.y * w.z; acc[1][3] += a.y * w.w;
      acc[2][0] += a.z * w.x; acc[2][1] += a.z * w.y; acc[2][2] += a.z * w.z; acc[2][3] += a.z * w.w;
      acc[3][0] += a.w * w.x; acc[3][1] += a.w * w.y; acc[3][2] += a.w * w.z; acc[3][3] += a.w * w.w;
    }
    __syncthreads();
  }
  const int n = n0 + nn4 * 4;
  float4 b1 = *(const float4*)&bih[n];
  float4 b2 = *(const float4*)&bhh[n];
  float4 bv = make_float4(b1.x + b2.x, b1.y + b2.y, b1.z + b2.z, b1.w + b2.w);
#pragma unroll
  for (int i = 0; i < 4; i++) {
    int t = t0 + tt4 * 4 + i;
    float4 o = make_float4(acc[i][0] + bv.x, acc[i][1] + bv.y,
                           acc[i][2] + bv.z, acc[i][3] + bv.w);
    *(float4*)&g_gx[(long)t * (BATCH * G4) + (long)b * G4 + n] = o;
  }
}

__global__ void init_bar() {
  ((volatile unsigned*)g_arrive)[threadIdx.x] = 0u;
}

__global__ void dummy_k() {}

// ---------------- phase 2: persistent recurrent scan ----------------
// NB=128 blocks x 512 threads. Block owns hidden cols j = blk*4 + {0..3},
// i.e. 16 W_hh rows resident in SMEM for all 1024 steps.
// Thread map: jj = tid&3 (hidden unit), bg = (tid>>2)&7 (batch group of 4),
// ks = tid>>5 (warp id = k-split of 16, 32 k each).
#define WPAD 516
#define RED_STRIDE 17
#define SM_W     (16 * WPAD)                    // 8256
#define SM_H     (32 * WPAD)                    // 16512
#define SM_RED   (16 * 32 * RED_STRIDE)         // 8704
#define SM_GXS   (32 * 4 * 4)                   // 512
#define SM_HOUT  (32 * 4)                       // 128
#define SMEM_SCAN_FLOATS (SM_W + SM_H + SM_RED + SM_GXS + SM_HOUT)
#define SMEM_SCAN_BYTES (SMEM_SCAN_FLOATS * 4)

__global__ __launch_bounds__(NT, 1) void lstm_scan(const float* __restrict__ Whh) {
  extern __shared__ float sm[];
  float* Wsm  = sm;
  float* hsm  = Wsm + SM_W;
  float* red  = hsm + SM_H;
  float* gxs  = red + SM_RED;
  float* hout = gxs + SM_GXS;

  const int tid = threadIdx.x, blk = blockIdx.x;
  const int jj = tid & 3, bg = (tid >> 2) & 7, ks = tid >> 5;

  // load persistent W_hh slice: rows r = g*512 + blk*4 + j4 -> Wsm[g*4+j4]
  for (int r = 0; r < 16; r++) {
    int g = r >> 2, j4 = r & 3;
    long row = (long)(g * HID + blk * 4 + j4) * HID;
    for (int k = tid; k < HID; k += NT) Wsm[r * WPAD + k] = Whh[row + k];
  }
  __syncthreads();

  const float* w0 = Wsm + (0  + jj) * WPAD + ks * 32;
  const float* w1 = Wsm + (4  + jj) * WPAD + ks * 32;
  const float* w2 = Wsm + (8  + jj) * WPAD + ks * 32;
  const float* w3 = Wsm + (12 + jj) * WPAD + ks * 32;

  float c_reg = 0.f;

  for (int t = 0; t < T_LEN; t++) {
    // ---- gx prefetch (vectorized, independent of h) ----
    float4 gxv;
    if (tid < 128) {
      int b = tid >> 2, g = tid & 3;
      gxv = *(const float4*)&g_gx[(long)t * (BATCH * G4) + (long)b * G4 + g * HID + blk * 4];
    }
    // ---- stage h(t-1) into SMEM via cp.async.cg ----
    if (t == 0) {
      for (int i = tid; i < SM_H; i += NT) hsm[i] = 0.f;
    } else {
      const float* src = g_hs + (long)(t - 1) * BH;
#pragma unroll
      for (int i = tid * 4; i < BH; i += NT * 4) {
        int b = i >> 9, k = i & 511;
        cp_async16(hsm + b * WPAD + k, src + i);
      }
      asm volatile("cp.async.commit_group;\n");
    }
    if (tid < 128) {
      int b = tid >> 2, g = tid & 3;
      *(float4*)&gxs[(b * 4 + g) * 4] = gxv;
    }
    if (t != 0) asm volatile("cp.async.wait_group 0;\n" ::: "memory");
    __syncthreads();

    // ---- per-thread partial GEMM over 32 k ----
    float acc[16];
#pragma unroll
    for (int q = 0; q < 16; q++) acc[q] = 0.f;
    {
      const float* hb = hsm + ks * 32;
#pragma unroll
      for (int kk = 0; kk < 32; kk += 4) {
        float4 wi = *(const float4*)(w0 + kk);
        float4 wf = *(const float4*)(w1 + kk);
        float4 wg = *(const float4*)(w2 + kk);
        float4 wo = *(const float4*)(w3 + kk);
#pragma unroll
        for (int b4 = 0; b4 < 4; b4++) {
          float4 hv = *(const float4*)(hb + (bg * 4 + b4) * WPAD + kk);
          acc[b4]      += wi.x * hv.x + wi.y * hv.y + wi.z * hv.z + wi.w * hv.w;
          acc[4 + b4]  += wf.x * hv.x + wf.y * hv.y + wf.z * hv.z + wf.w * hv.w;
          acc[8 + b4]  += wg.x * hv.x + wg.y * hv.y + wg.z * hv.z + wg.w * hv.w;
          acc[12 + b4] += wo.x * hv.x + wo.y * hv.y + wo.z * hv.z + wo.w * hv.w;
        }
      }
    }
    // ---- conflict-free spill (stride 17) ----
    {
      float* rp = red + (ks * 32 + (tid & 31)) * RED_STRIDE;
#pragma unroll
      for (int q = 0; q < 16; q++) rp[q] = acc[q];
    }
    __syncthreads();

    // ---- reduce + gates: thread (tid<128) owns (b = tid>>2, j = blk*4 + tid&3)
    if (tid < 128) {
      const int b = tid >> 2, j = tid & 3;
      const int cellp = ((b >> 2) << 2) | j;   // writer's tid&31 for this (bg,jj)
      const int b4 = b & 3;
      float s0 = gxs[(b * 4 + 0) * 4 + j];
      float s1 = gxs[(b * 4 + 1) * 4 + j];
      float s2 = gxs[(b * 4 + 2) * 4 + j];
      float s3 = gxs[(b * 4 + 3) * 4 + j];
#pragma unroll
      for (int p = 0; p < 16; p++) {
        const float* q = red + (p * 32 + cellp) * RED_STRIDE + b4;
        s0 += q[0]; s1 += q[4]; s2 += q[8]; s3 += q[12];
      }
      float ig = fast_sig(s0);
      float fg = fast_sig(s1);
      float gg = fast_tanh(s2);
      float og = fast_sig(s3);
      c_reg = fg * c_reg + ig * gg;
      float h = og * fast_tanh(c_reg);
      hout[b * 4 + j] = h;
    }
    __syncthreads();

    // ---- warp 0: contiguous h store + flag + poll ----
    if (tid < 32) {
      float4 hv = *(const float4*)&hout[tid * 4];
      *(float4*)&g_hs[(long)t * BH + tid * HID + blk * 4] = hv;
      __syncwarp();
      if (tid == 0) {
        __threadfence();
        ((volatile unsigned*)g_arrive)[blk] = (unsigned)(t + 1);
      }
      const unsigned target = (unsigned)(t + 1);
      const volatile unsigned* fl = (const volatile unsigned*)g_arrive;
      bool ok;
      do {
        unsigned a = fl[tid], b = fl[tid + 32], c = fl[tid + 64], d = fl[tid + 96];
        ok = __all_sync(0xffffffffu,
                        (a >= target) && (b >= target) && (c >= target) && (d >= target));
      } while (!ok);
    }
    __syncthreads();
  }
}

// ---------------- phase 3: transpose hs[T][B][H] -> out[B][H][T] ------------
__global__ __launch_bounds__(256) void transpose_hs(float* __restrict__ out) {
  __shared__ float tile[32][33];
  const int t0 = blockIdx.x * 32, j0 = blockIdx.y * 32, b = blockIdx.z;
  const int tx = threadIdx.x, ty = threadIdx.y;
  for (int i = ty; i < 32; i += 8)
    tile[i][tx] = g_hs[(long)(t0 + i) * BH + (long)b * HID + j0 + tx];
  __syncthreads();
  for (int i = ty; i < 32; i += 8)
    out[((long)b * HID + j0 + i) * T_LEN + t0 + tx] = tile[tx][i];
}

// ---------------- launch ----------------
extern "C" void kernel_launch(void* const* d_in, const int* in_sizes, int n_in,
                              void* d_out, int out_size) {
  (void)in_sizes; (void)n_in; (void)out_size;
  const float* x   = (const float*)d_in[0];
  const float* Wih = (const float*)d_in[1];
  const float* Whh = (const float*)d_in[2];
  const float* bih = (const float*)d_in[3];
  const float* bhh = (const float*)d_in[4];
  float* out = (float*)d_out;

  cudaFuncSetAttribute(lstm_scan, cudaFuncAttributeMaxDynamicSharedMemorySize,
                       SMEM_SCAN_BYTES);

  dim3 g1(T_LEN / 64, G4 / 64, BATCH);
  gemm_input<<<g1, 256>>>(x, Wih, bih, bhh);

  init_bar<<<1, NB>>>();
  // dummy launches: position lstm_scan as the 6th kernel launch so the fixed
  // `ncu -s 5 -c 1` window captures the scan kernel, not the transpose.
  dummy_k<<<1, 32>>>();
  dummy_k<<<1, 32>>>();
  dummy_k<<<1, 32>>>();
  lstm_scan<<<NB, NT, SMEM_SCAN_BYTES>>>(Whh);

  dim3 g3(T_LEN / 32, HID / 32, BATCH);
  transpose_hs<<<g3, dim3(32, 8)>>>(out);
}